// round 16
// baseline (speedup 1.0000x reference)
#include <cuda_runtime.h>
#include <cuda_bf16.h>
#include <cstdint>

#define NN 100000
#define NE 1600000
#define DIM 128
#define SLOTS 128
#define MT 256                          // M tile per block (8 row-groups x 32)
#define GRID_MMA ((NN + MT - 1) / MT)   // 391

typedef unsigned long long u64;

// ---------------------------------------------------------------------------
// Scratch (__device__ globals)
// ---------------------------------------------------------------------------
__device__ float g_mean[NN * DIM];
__device__ float g_h1[NN * DIM];
__device__ float g_h2[NN * DIM];
__device__ int   g_cursor[NN];
__device__ int   g_csrsrc[NN * SLOTS];
// pre-split, pre-SWIZZLED transposed weights: [matrix 0..5][hi/lo][128x128 bf16]
__device__ __nv_bfloat16 g_wbf[6][2][DIM * DIM];

// ---------------------------------------------------------------------------
// helpers
// ---------------------------------------------------------------------------
__device__ __forceinline__ uint32_t smem_u32(const void* p) {
    uint32_t a;
    asm("{ .reg .u64 t; cvta.to.shared.u64 t, %1; cvt.u32.u64 %0, t; }" : "=r"(a) : "l"(p));
    return a;
}
// XOR-swizzled byte offset inside a [rows x 128 bf16] tile (256B rows).
__device__ __forceinline__ uint32_t swz(uint32_t row, uint32_t kb) {
    return row * 256u + (((kb & ~15u) ^ ((row & 7u) << 4)) | (kb & 15u));
}
__device__ __forceinline__ void ldmatrix_x4(uint32_t* r, uint32_t addr) {
    asm volatile("ldmatrix.sync.aligned.m8n8.x4.shared.b16 {%0,%1,%2,%3}, [%4];"
                 : "=r"(r[0]), "=r"(r[1]), "=r"(r[2]), "=r"(r[3]) : "r"(addr));
}
__device__ __forceinline__ void mma_bf16(float* d, const uint32_t* a, const uint32_t* b) {
    asm volatile(
        "mma.sync.aligned.m16n8k16.row.col.f32.bf16.bf16.f32 "
        "{%0,%1,%2,%3}, {%4,%5,%6,%7}, {%8,%9}, {%0,%1,%2,%3};"
        : "+f"(d[0]), "+f"(d[1]), "+f"(d[2]), "+f"(d[3])
        : "r"(a[0]), "r"(a[1]), "r"(a[2]), "r"(a[3]), "r"(b[0]), "r"(b[1]));
}

// ---------------------------------------------------------------------------
// prep: cursor init + 6 weight matrices -> transposed, split, swizzled
// ---------------------------------------------------------------------------
#define NB_INIT ((NN + 255) / 256)

__global__ void k_prep(const float* W0, const float* W1, const float* W2,
                       const float* W3, const float* W4, const float* W5) {
    int b = blockIdx.x;
    if (b < NB_INIT) {
        int i = b * 256 + threadIdx.x;
        if (i < NN) g_cursor[i] = i * SLOTS;
        return;
    }
    int m = b - NB_INIT;
    const float* W = (m == 0) ? W0 : (m == 1) ? W1 : (m == 2) ? W2
                     : (m == 3) ? W3 : (m == 4) ? W4 : W5;
    char* ih = (char*)&g_wbf[m][0][0];
    char* il = (char*)&g_wbf[m][1][0];
    for (int e = threadIdx.x; e < DIM * DIM; e += 256) {
        int n = e >> 7, k = e & 127;
        float v = __ldg(W + k * DIM + n);           // BT[n][k] = W[k][n]
        __nv_bfloat16 h = __float2bfloat16(v);
        __nv_bfloat16 l = __float2bfloat16(v - __bfloat162float(h));
        uint32_t o = swz((uint32_t)n, (uint32_t)(k * 2));
        *(__nv_bfloat16*)(ih + o) = h;
        *(__nv_bfloat16*)(il + o) = l;
    }
}

__global__ void k_bucket(const int* __restrict__ src, const int* __restrict__ dst) {
    int e = blockIdx.x * blockDim.x + threadIdx.x;
    if (e < NE) {
        int d = dst[e];
        int pos = atomicAdd(&g_cursor[d], 1);
        if (pos < d * SLOTS + SLOTS)
            g_csrsrc[pos] = src[e];
    }
}

// ---------------------------------------------------------------------------
// pull-mode mean aggregation: one warp per node.
// ---------------------------------------------------------------------------
__global__ void __launch_bounds__(256)
k_agg(const float* __restrict__ x, float* __restrict__ mean) {
    int node = (blockIdx.x * blockDim.x + threadIdx.x) >> 5;
    int lane = threadIdx.x & 31;
    if (node >= NN) return;
    int beg = node * SLOTS;
    int d   = min(__ldg(g_cursor + node) - beg, SLOTS);
    int end = beg + d;

    const float4* xv = (const float4*)x;
    float4 acc = make_float4(0.f, 0.f, 0.f, 0.f);
    for (int e = beg; e < end; e += 8) {
        int idx[8];
#pragma unroll
        for (int j = 0; j < 8; ++j)
            idx[j] = (e + j < end) ? __ldg(g_csrsrc + e + j) : -1;
#pragma unroll
        for (int j = 0; j < 8; ++j) {
            if (idx[j] >= 0) {
                float4 v = __ldg(xv + (size_t)idx[j] * 32 + lane);
                acc.x += v.x; acc.y += v.y; acc.z += v.z; acc.w += v.w;
            }
        }
    }
    float inv = (d > 0) ? (1.0f / (float)d) : 0.0f;
    acc.x *= inv; acc.y *= inv; acc.z *= inv; acc.w *= inv;
    ((float4*)(mean + (size_t)node * DIM))[lane] = acc;
}

// ---------------------------------------------------------------------------
// tensor-core SAGE GEMM (mma.sync bf16 split), MT=256, 512 thr, 16 warps:
//   warp tile 32 rows x 64 cols (2 m16 x 8 n8) -> MMA/LDSM ratio 4.0
//   (12 ldmatrix.x4 per k0 for 48 MMAs) vs R15's 3.0. Total LDSM -25%.
// SMEM 196,608B: AH(64K) AL(64K) + current-phase B hi/lo (2x32K, restaged
// per phase — measured free). XOR swizzle, 256B rows.
// ---------------------------------------------------------------------------
template <bool RELU>
__global__ void __launch_bounds__(512)
k_mma(const float* __restrict__ mean, const float* __restrict__ hin,
      const __nv_bfloat16* __restrict__ wl_h, const __nv_bfloat16* __restrict__ wl_l,
      const __nv_bfloat16* __restrict__ wr_h, const __nv_bfloat16* __restrict__ wr_l,
      const float* __restrict__ bias, float* __restrict__ out) {
    extern __shared__ char sm[];
    constexpr uint32_t ATILE_B = MT * 256;        // 65536 B per split half
    constexpr uint32_t BTILE_B = DIM * 256;       // 32768 B
    char* sAH = sm;
    char* sAL = sm + ATILE_B;
    char* sB  = sm + 2 * ATILE_B;
    const uint32_t base = smem_u32(sm);
    const uint32_t AH = base, AL = base + ATILE_B;
    const uint32_t BH = base + 2 * ATILE_B;
    const uint32_t BL = BH + BTILE_B;

    const int tid  = threadIdx.x;
    const int wid  = tid >> 5;
    const int lane = tid & 31;
    const int row0 = blockIdx.x * MT;
    const int wrow = (wid >> 1) * 32;     // warp's 32 rows (8 groups)
    const int ncol = (wid & 1) * 64;      // warp's 64-col half

    const uint32_t arow0 = (uint32_t)(wrow + ((lane >> 3) & 1) * 8 + (lane & 7));
    const uint32_t aklane = ((lane >> 4) & 1) * 16;
    const uint32_t axm = (arow0 & 7u) << 4;
    const uint32_t brow0 = (uint32_t)(ncol + ((lane >> 4) & 1) * 8 + (lane & 7));
    const uint32_t bklane = ((lane >> 3) & 1) * 16;
    const uint32_t bxm = (brow0 & 7u) << 4;

    float d[2][8][4];
#pragma unroll
    for (int m = 0; m < 2; ++m)
#pragma unroll
        for (int n = 0; n < 8; ++n)
#pragma unroll
            for (int j = 0; j < 4; ++j) d[m][n][j] = 0.f;

#pragma unroll
    for (int phase = 0; phase < 2; ++phase) {
        const float* A = phase ? hin : mean;
        const __nv_bfloat16* WH = phase ? wr_h : wl_h;
        const __nv_bfloat16* WL = phase ? wr_l : wl_l;

        __syncthreads();   // all warps done reading previous phase's smem
        // stage A: split f32 -> hi/lo bf16, swizzled (8192 float4 / 512 thr)
        for (int t = tid; t < MT * 32; t += 512) {
            int r  = t >> 5;
            uint32_t kb = (uint32_t)(t & 31) * 8;
            int grow = row0 + r;
            float4 v = make_float4(0.f, 0.f, 0.f, 0.f);
            if (grow < NN)
                v = __ldg((const float4*)(A + (size_t)grow * DIM) + (t & 31));
            __nv_bfloat16 h0 = __float2bfloat16(v.x), h1 = __float2bfloat16(v.y),
                          h2 = __float2bfloat16(v.z), h3 = __float2bfloat16(v.w);
            __nv_bfloat16 l0 = __float2bfloat16(v.x - __bfloat162float(h0));
            __nv_bfloat16 l1 = __float2bfloat16(v.y - __bfloat162float(h1));
            __nv_bfloat16 l2 = __float2bfloat16(v.z - __bfloat162float(h2));
            __nv_bfloat16 l3 = __float2bfloat16(v.w - __bfloat162float(h3));
            uint2 hp, lp;
            hp.x = (uint32_t)__bfloat16_as_ushort(h0) | ((uint32_t)__bfloat16_as_ushort(h1) << 16);
            hp.y = (uint32_t)__bfloat16_as_ushort(h2) | ((uint32_t)__bfloat16_as_ushort(h3) << 16);
            lp.x = (uint32_t)__bfloat16_as_ushort(l0) | ((uint32_t)__bfloat16_as_ushort(l1) << 16);
            lp.y = (uint32_t)__bfloat16_as_ushort(l2) | ((uint32_t)__bfloat16_as_ushort(l3) << 16);
            uint32_t o = swz((uint32_t)r, kb);
            *(uint2*)(sAH + o) = hp;
            *(uint2*)(sAL + o) = lp;
        }
        // stage this phase's weight tiles (swizzled images, raw copy)
        {
            const uint4* srcH = (const uint4*)WH;
            const uint4* srcL = (const uint4*)WL;
            uint4* dst = (uint4*)sB;
            constexpr int C = BTILE_B / 16;        // 2048 uint4 per tile
            for (int t = tid; t < C; t += 512) {
                dst[t]     = __ldg(srcH + t);
                dst[t + C] = __ldg(srcL + t);
            }
        }
        __syncthreads();

#pragma unroll
        for (int k0 = 0; k0 < DIM; k0 += 16) {
            const uint32_t akb = (uint32_t)(k0 * 2);
            uint32_t ah[2][4], al[2][4];
#pragma unroll
            for (int m = 0; m < 2; ++m) {
                uint32_t ao = (arow0 + m * 16) * 256 + ((akb + aklane) ^ axm);
                ldmatrix_x4(ah[m], AH + ao);
                ldmatrix_x4(al[m], AL + ao);
            }
#pragma unroll
            for (int np = 0; np < 4; ++np) {
                uint32_t bo = (brow0 + np * 16) * 256 + ((akb + bklane) ^ bxm);
                uint32_t bh[4], bl[4];
                ldmatrix_x4(bh, BH + bo);
                ldmatrix_x4(bl, BL + bo);
#pragma unroll
                for (int m = 0; m < 2; ++m) {
                    mma_bf16(d[m][np * 2],     ah[m], bh);
                    mma_bf16(d[m][np * 2],     ah[m], bl);
                    mma_bf16(d[m][np * 2],     al[m], bh);
                    mma_bf16(d[m][np * 2 + 1], ah[m], bh + 2);
                    mma_bf16(d[m][np * 2 + 1], ah[m], bl + 2);
                    mma_bf16(d[m][np * 2 + 1], al[m], bh + 2);
                }
            }
        }
    }

    // epilogue
    const int cb = (lane & 3) * 2;
#pragma unroll
    for (int m = 0; m < 2; ++m) {
        int r0g = row0 + wrow + m * 16 + (lane >> 2);
        int r1g = r0g + 8;
#pragma unroll
        for (int n = 0; n < 8; ++n) {
            int col = ncol + n * 8 + cb;
            float2 bb = *(const float2*)(bias + col);
            float v0 = d[m][n][0] + bb.x, v1 = d[m][n][1] + bb.y;
            float v2 = d[m][n][2] + bb.x, v3 = d[m][n][3] + bb.y;
            if (RELU) {
                v0 = fmaxf(v0, 0.f); v1 = fmaxf(v1, 0.f);
                v2 = fmaxf(v2, 0.f); v3 = fmaxf(v3, 0.f);
            }
            if (r0g < NN) *(float2*)(out + (size_t)r0g * DIM + col) = make_float2(v0, v1);
            if (r1g < NN) *(float2*)(out + (size_t)r1g * DIM + col) = make_float2(v2, v3);
        }
    }
}

// ---------------------------------------------------------------------------
// kernel_launch — launch 3 = k_mma layer 1 (ncu target)
// inputs: t, x, edge_index, W1_l, W1_r, b1, W2_l, W2_r, b2, W3_l, W3_r, b3
// ---------------------------------------------------------------------------
extern "C" void kernel_launch(void* const* d_in, const int* in_sizes, int n_in,
                              void* d_out, int out_size) {
    const float* x   = (const float*)d_in[1];
    const int*   ei  = (const int*)d_in[2];
    const int*   src = ei;
    const int*   dst = ei + NE;
    const float* W1l = (const float*)d_in[3];
    const float* W1r = (const float*)d_in[4];
    const float* b1  = (const float*)d_in[5];
    const float* W2l = (const float*)d_in[6];
    const float* W2r = (const float*)d_in[7];
    const float* b2  = (const float*)d_in[8];
    const float* W3l = (const float*)d_in[9];
    const float* W3r = (const float*)d_in[10];
    const float* b3  = (const float*)d_in[11];
    float* out = (float*)d_out;

    float *mean, *h1, *h2;
    cudaGetSymbolAddress((void**)&mean, g_mean);
    cudaGetSymbolAddress((void**)&h1,  g_h1);
    cudaGetSymbolAddress((void**)&h2,  g_h2);
    __nv_bfloat16* wbf;
    cudaGetSymbolAddress((void**)&wbf, g_wbf);
    auto img = [&](int m, int hl) { return wbf + ((size_t)m * 2 + hl) * DIM * DIM; };

    const int SMEM = 2 * MT * 256 + 2 * DIM * 256;   // 131072 + 65536 = 196608 B
    cudaFuncSetAttribute(k_mma<true>,  cudaFuncAttributeMaxDynamicSharedMemorySize, SMEM);
    cudaFuncSetAttribute(k_mma<false>, cudaFuncAttributeMaxDynamicSharedMemorySize, SMEM);

    const int AGG_BLOCKS = (NN * 32 + 255) / 256;

    // launches 0-1: prep (cursors + weight split/swizzle), bucket
    k_prep<<<NB_INIT + 6, 256>>>(W1l, W1r, W2l, W2r, W3l, W3r);
    k_bucket<<<(NE + 255) / 256, 256>>>(src, dst);

    // layer 1 (launch 2 = agg, launch 3 = mma -> ncu)
    k_agg<<<AGG_BLOCKS, 256>>>(x, mean);
    k_mma<true><<<GRID_MMA, 512, SMEM>>>(mean, x, img(0,0), img(0,1), img(1,0), img(1,1), b1, h1);

    // layer 2
    k_agg<<<AGG_BLOCKS, 256>>>(h1, mean);
    k_mma<true><<<GRID_MMA, 512, SMEM>>>(mean, h1, img(2,0), img(2,1), img(3,0), img(3,1), b2, h2);

    // layer 3 (no relu)
    k_agg<<<AGG_BLOCKS, 256>>>(h2, mean);
    k_mma<false><<<GRID_MMA, 512, SMEM>>>(mean, h2, img(4,0), img(4,1), img(5,0), img(5,1), b3, out);
}

// round 17
// speedup vs baseline: 1.1285x; 1.1285x over previous
#include <cuda_runtime.h>
#include <cuda_bf16.h>
#include <cstdint>

#define NN 100000
#define NE 1600000
#define DIM 128
#define SLOTS 128
#define MT 96                           // M tile per block (3 row-groups x 32)
#define GRID_MMA ((NN + MT - 1) / MT)   // 1042

typedef unsigned long long u64;

// ---------------------------------------------------------------------------
// Scratch (__device__ globals)
// ---------------------------------------------------------------------------
__device__ float g_mean[NN * DIM];
__device__ float g_h1[NN * DIM];
__device__ float g_h2[NN * DIM];
__device__ int   g_cursor[NN];
__device__ int   g_csrsrc[NN * SLOTS];
// pre-split, pre-SWIZZLED transposed weights: [matrix 0..5][hi/lo][128x128 bf16]
__device__ __nv_bfloat16 g_wbf[6][2][DIM * DIM];

// ---------------------------------------------------------------------------
// helpers
// ---------------------------------------------------------------------------
__device__ __forceinline__ uint32_t smem_u32(const void* p) {
    uint32_t a;
    asm("{ .reg .u64 t; cvta.to.shared.u64 t, %1; cvt.u32.u64 %0, t; }" : "=r"(a) : "l"(p));
    return a;
}
// XOR-swizzled byte offset inside a [rows x 128 bf16] tile (256B rows).
__device__ __forceinline__ uint32_t swz(uint32_t row, uint32_t kb) {
    return row * 256u + (((kb & ~15u) ^ ((row & 7u) << 4)) | (kb & 15u));
}
__device__ __forceinline__ void ldmatrix_x4(uint32_t* r, uint32_t addr) {
    asm volatile("ldmatrix.sync.aligned.m8n8.x4.shared.b16 {%0,%1,%2,%3}, [%4];"
                 : "=r"(r[0]), "=r"(r[1]), "=r"(r[2]), "=r"(r[3]) : "r"(addr));
}
__device__ __forceinline__ void mma_bf16(float* d, const uint32_t* a, const uint32_t* b) {
    asm volatile(
        "mma.sync.aligned.m16n8k16.row.col.f32.bf16.bf16.f32 "
        "{%0,%1,%2,%3}, {%4,%5,%6,%7}, {%8,%9}, {%0,%1,%2,%3};"
        : "+f"(d[0]), "+f"(d[1]), "+f"(d[2]), "+f"(d[3])
        : "r"(a[0]), "r"(a[1]), "r"(a[2]), "r"(a[3]), "r"(b[0]), "r"(b[1]));
}

// ---------------------------------------------------------------------------
// prep: cursor init + 6 weight matrices -> transposed, split, swizzled
// ---------------------------------------------------------------------------
#define NB_INIT ((NN + 255) / 256)

__global__ void k_prep(const float* W0, const float* W1, const float* W2,
                       const float* W3, const float* W4, const float* W5) {
    int b = blockIdx.x;
    if (b < NB_INIT) {
        int i = b * 256 + threadIdx.x;
        if (i < NN) g_cursor[i] = i * SLOTS;
        return;
    }
    int m = b - NB_INIT;
    const float* W = (m == 0) ? W0 : (m == 1) ? W1 : (m == 2) ? W2
                     : (m == 3) ? W3 : (m == 4) ? W4 : W5;
    char* ih = (char*)&g_wbf[m][0][0];
    char* il = (char*)&g_wbf[m][1][0];
    for (int e = threadIdx.x; e < DIM * DIM; e += 256) {
        int n = e >> 7, k = e & 127;
        float v = __ldg(W + k * DIM + n);           // BT[n][k] = W[k][n]
        __nv_bfloat16 h = __float2bfloat16(v);
        __nv_bfloat16 l = __float2bfloat16(v - __bfloat162float(h));
        uint32_t o = swz((uint32_t)n, (uint32_t)(k * 2));
        *(__nv_bfloat16*)(ih + o) = h;
        *(__nv_bfloat16*)(il + o) = l;
    }
}

__global__ void k_bucket(const int* __restrict__ src, const int* __restrict__ dst) {
    int e = blockIdx.x * blockDim.x + threadIdx.x;
    if (e < NE) {
        int d = dst[e];
        int pos = atomicAdd(&g_cursor[d], 1);
        if (pos < d * SLOTS + SLOTS)
            g_csrsrc[pos] = src[e];
    }
}

// ---------------------------------------------------------------------------
// pull-mode mean aggregation: one warp per node.
// ---------------------------------------------------------------------------
__global__ void __launch_bounds__(256)
k_agg(const float* __restrict__ x, float* __restrict__ mean) {
    int node = (blockIdx.x * blockDim.x + threadIdx.x) >> 5;
    int lane = threadIdx.x & 31;
    if (node >= NN) return;
    int beg = node * SLOTS;
    int d   = min(__ldg(g_cursor + node) - beg, SLOTS);
    int end = beg + d;

    const float4* xv = (const float4*)x;
    float4 acc = make_float4(0.f, 0.f, 0.f, 0.f);
    for (int e = beg; e < end; e += 8) {
        int idx[8];
#pragma unroll
        for (int j = 0; j < 8; ++j)
            idx[j] = (e + j < end) ? __ldg(g_csrsrc + e + j) : -1;
#pragma unroll
        for (int j = 0; j < 8; ++j) {
            if (idx[j] >= 0) {
                float4 v = __ldg(xv + (size_t)idx[j] * 32 + lane);
                acc.x += v.x; acc.y += v.y; acc.z += v.z; acc.w += v.w;
            }
        }
    }
    float inv = (d > 0) ? (1.0f / (float)d) : 0.0f;
    acc.x *= inv; acc.y *= inv; acc.z *= inv; acc.w *= inv;
    ((float4*)(mean + (size_t)node * DIM))[lane] = acc;
}

// ---------------------------------------------------------------------------
// tensor-core SAGE GEMM (mma.sync bf16 split), MT=96, 384 thr, 12 warps,
// 2 BLOCKS/SM:
//   warp tile 32x32 (ratio 3.0, same per-warp economics as R15) but smem
//   cut to 114,688B so TWO blocks co-reside per SM — one block's A-staging
//   (LDG + split + STS bursts) overlaps the other block's MMA loop, removing
//   staging from the critical path that R15's 1-block/SM config exposed.
// SMEM: AH(24K) AL(24K) + current-phase B hi/lo (2x32K, restaged per phase).
// ---------------------------------------------------------------------------
template <bool RELU>
__global__ void __launch_bounds__(384, 2)
k_mma(const float* __restrict__ mean, const float* __restrict__ hin,
      const __nv_bfloat16* __restrict__ wl_h, const __nv_bfloat16* __restrict__ wl_l,
      const __nv_bfloat16* __restrict__ wr_h, const __nv_bfloat16* __restrict__ wr_l,
      const float* __restrict__ bias, float* __restrict__ out) {
    extern __shared__ char sm[];
    constexpr uint32_t ATILE_B = MT * 256;        // 24576 B per split half
    constexpr uint32_t BTILE_B = DIM * 256;       // 32768 B
    char* sAH = sm;
    char* sAL = sm + ATILE_B;
    char* sB  = sm + 2 * ATILE_B;
    const uint32_t base = smem_u32(sm);
    const uint32_t AH = base, AL = base + ATILE_B;
    const uint32_t BH = base + 2 * ATILE_B;
    const uint32_t BL = BH + BTILE_B;

    const int tid  = threadIdx.x;
    const int wid  = tid >> 5;
    const int lane = tid & 31;
    const int row0 = blockIdx.x * MT;
    const int wrow = (wid >> 2) * 32;     // warp's 32 rows (3 groups)
    const int ncol = (wid & 3) * 32;      // warp's 32 cols

    const uint32_t arow0 = (uint32_t)(wrow + ((lane >> 3) & 1) * 8 + (lane & 7));
    const uint32_t aklane = ((lane >> 4) & 1) * 16;
    const uint32_t axm = (arow0 & 7u) << 4;
    const uint32_t brow0 = (uint32_t)(ncol + ((lane >> 4) & 1) * 8 + (lane & 7));
    const uint32_t bklane = ((lane >> 3) & 1) * 16;
    const uint32_t bxm = (brow0 & 7u) << 4;

    float d[2][4][4];
#pragma unroll
    for (int m = 0; m < 2; ++m)
#pragma unroll
        for (int n = 0; n < 4; ++n)
#pragma unroll
            for (int j = 0; j < 4; ++j) d[m][n][j] = 0.f;

#pragma unroll
    for (int phase = 0; phase < 2; ++phase) {
        const float* A = phase ? hin : mean;
        const __nv_bfloat16* WH = phase ? wr_h : wl_h;
        const __nv_bfloat16* WL = phase ? wr_l : wl_l;

        __syncthreads();
        // stage A: split f32 -> hi/lo bf16, swizzled (3072 float4 / 384 thr)
        for (int t = tid; t < MT * 32; t += 384) {
            int r  = t >> 5;
            uint32_t kb = (uint32_t)(t & 31) * 8;
            int grow = row0 + r;
            float4 v = make_float4(0.f, 0.f, 0.f, 0.f);
            if (grow < NN)
                v = __ldg((const float4*)(A + (size_t)grow * DIM) + (t & 31));
            __nv_bfloat16 h0 = __float2bfloat16(v.x), h1 = __float2bfloat16(v.y),
                          h2 = __float2bfloat16(v.z), h3 = __float2bfloat16(v.w);
            __nv_bfloat16 l0 = __float2bfloat16(v.x - __bfloat162float(h0));
            __nv_bfloat16 l1 = __float2bfloat16(v.y - __bfloat162float(h1));
            __nv_bfloat16 l2 = __float2bfloat16(v.z - __bfloat162float(h2));
            __nv_bfloat16 l3 = __float2bfloat16(v.w - __bfloat162float(h3));
            uint2 hp, lp;
            hp.x = (uint32_t)__bfloat16_as_ushort(h0) | ((uint32_t)__bfloat16_as_ushort(h1) << 16);
            hp.y = (uint32_t)__bfloat16_as_ushort(h2) | ((uint32_t)__bfloat16_as_ushort(h3) << 16);
            lp.x = (uint32_t)__bfloat16_as_ushort(l0) | ((uint32_t)__bfloat16_as_ushort(l1) << 16);
            lp.y = (uint32_t)__bfloat16_as_ushort(l2) | ((uint32_t)__bfloat16_as_ushort(l3) << 16);
            uint32_t o = swz((uint32_t)r, kb);
            *(uint2*)(sAH + o) = hp;
            *(uint2*)(sAL + o) = lp;
        }
        // stage this phase's weight tiles (swizzled images, raw copy)
        {
            const uint4* srcH = (const uint4*)WH;
            const uint4* srcL = (const uint4*)WL;
            uint4* dst = (uint4*)sB;
            constexpr int C = BTILE_B / 16;        // 2048 uint4 per tile
            for (int t = tid; t < C; t += 384) {
                dst[t]     = __ldg(srcH + t);
                dst[t + C] = __ldg(srcL + t);
            }
        }
        __syncthreads();

#pragma unroll
        for (int k0 = 0; k0 < DIM; k0 += 16) {
            const uint32_t akb = (uint32_t)(k0 * 2);
            uint32_t ah[2][4], al[2][4];
#pragma unroll
            for (int m = 0; m < 2; ++m) {
                uint32_t ao = (arow0 + m * 16) * 256 + ((akb + aklane) ^ axm);
                ldmatrix_x4(ah[m], AH + ao);
                ldmatrix_x4(al[m], AL + ao);
            }
#pragma unroll
            for (int np = 0; np < 2; ++np) {
                uint32_t bo = (brow0 + np * 16) * 256 + ((akb + bklane) ^ bxm);
                uint32_t bh[4], bl[4];
                ldmatrix_x4(bh, BH + bo);
                ldmatrix_x4(bl, BL + bo);
#pragma unroll
                for (int m = 0; m < 2; ++m) {
                    mma_bf16(d[m][np * 2],     ah[m], bh);
                    mma_bf16(d[m][np * 2],     ah[m], bl);
                    mma_bf16(d[m][np * 2],     al[m], bh);
                    mma_bf16(d[m][np * 2 + 1], ah[m], bh + 2);
                    mma_bf16(d[m][np * 2 + 1], ah[m], bl + 2);
                    mma_bf16(d[m][np * 2 + 1], al[m], bh + 2);
                }
            }
        }
    }

    // epilogue
    const int cb = (lane & 3) * 2;
#pragma unroll
    for (int m = 0; m < 2; ++m) {
        int r0g = row0 + wrow + m * 16 + (lane >> 2);
        int r1g = r0g + 8;
#pragma unroll
        for (int n = 0; n < 4; ++n) {
            int col = ncol + n * 8 + cb;
            float2 bb = *(const float2*)(bias + col);
            float v0 = d[m][n][0] + bb.x, v1 = d[m][n][1] + bb.y;
            float v2 = d[m][n][2] + bb.x, v3 = d[m][n][3] + bb.y;
            if (RELU) {
                v0 = fmaxf(v0, 0.f); v1 = fmaxf(v1, 0.f);
                v2 = fmaxf(v2, 0.f); v3 = fmaxf(v3, 0.f);
            }
            if (r0g < NN) *(float2*)(out + (size_t)r0g * DIM + col) = make_float2(v0, v1);
            if (r1g < NN) *(float2*)(out + (size_t)r1g * DIM + col) = make_float2(v2, v3);
        }
    }
}

// ---------------------------------------------------------------------------
// kernel_launch — launch 3 = k_mma layer 1 (ncu target)
// inputs: t, x, edge_index, W1_l, W1_r, b1, W2_l, W2_r, b2, W3_l, W3_r, b3
// ---------------------------------------------------------------------------
extern "C" void kernel_launch(void* const* d_in, const int* in_sizes, int n_in,
                              void* d_out, int out_size) {
    const float* x   = (const float*)d_in[1];
    const int*   ei  = (const int*)d_in[2];
    const int*   src = ei;
    const int*   dst = ei + NE;
    const float* W1l = (const float*)d_in[3];
    const float* W1r = (const float*)d_in[4];
    const float* b1  = (const float*)d_in[5];
    const float* W2l = (const float*)d_in[6];
    const float* W2r = (const float*)d_in[7];
    const float* b2  = (const float*)d_in[8];
    const float* W3l = (const float*)d_in[9];
    const float* W3r = (const float*)d_in[10];
    const float* b3  = (const float*)d_in[11];
    float* out = (float*)d_out;

    float *mean, *h1, *h2;
    cudaGetSymbolAddress((void**)&mean, g_mean);
    cudaGetSymbolAddress((void**)&h1,  g_h1);
    cudaGetSymbolAddress((void**)&h2,  g_h2);
    __nv_bfloat16* wbf;
    cudaGetSymbolAddress((void**)&wbf, g_wbf);
    auto img = [&](int m, int hl) { return wbf + ((size_t)m * 2 + hl) * DIM * DIM; };

    const int SMEM = 2 * MT * 256 + 2 * DIM * 256;   // 49152 + 65536 = 114688 B
    cudaFuncSetAttribute(k_mma<true>,  cudaFuncAttributeMaxDynamicSharedMemorySize, SMEM);
    cudaFuncSetAttribute(k_mma<false>, cudaFuncAttributeMaxDynamicSharedMemorySize, SMEM);

    const int AGG_BLOCKS = (NN * 32 + 255) / 256;

    // launches 0-1: prep (cursors + weight split/swizzle), bucket
    k_prep<<<NB_INIT + 6, 256>>>(W1l, W1r, W2l, W2r, W3l, W3r);
    k_bucket<<<(NE + 255) / 256, 256>>>(src, dst);

    // layer 1 (launch 2 = agg, launch 3 = mma -> ncu)
    k_agg<<<AGG_BLOCKS, 256>>>(x, mean);
    k_mma<true><<<GRID_MMA, 384, SMEM>>>(mean, x, img(0,0), img(0,1), img(1,0), img(1,1), b1, h1);

    // layer 2
    k_agg<<<AGG_BLOCKS, 256>>>(h1, mean);
    k_mma<true><<<GRID_MMA, 384, SMEM>>>(mean, h1, img(2,0), img(2,1), img(3,0), img(3,1), b2, h2);

    // layer 3 (no relu)
    k_agg<<<AGG_BLOCKS, 256>>>(h2, mean);
    k_mma<false><<<GRID_MMA, 384, SMEM>>>(mean, h2, img(4,0), img(4,1), img(5,0), img(5,1), b3, out);
}